// round 5
// baseline (speedup 1.0000x reference)
#include <cuda_runtime.h>
#include <math.h>

#define NTHREADS 128
#define PAIRS    16
#define ROWS     48        // PAIRS*3
#define NBLK     2048      // 32768/PAIRS

typedef unsigned long long ull;

// ---------------------------------------------------------------------------
// smem layout (floats): 16704 floats = 66816 B -> 3 blocks/SM (200KB)
// ---------------------------------------------------------------------------
#define EVT_OFF   0        // 48*176 = 8448
#define FEAT_OFF  8448     // 48*128 = 6144
#define ABUF_OFF  14592    // 48*44  = 2112
#define SMEM_FLOATS 16704
#define SMEM_BYTES (SMEM_FLOATS*4)
// aliases inside EVT region (evt dead after gine pass 2 consumes it)
#define TGTB_OFF  0        // 32x128
#define WQ_OFF    4096     // 32x128
#define WP_OFF    0        // 16x128 (tgtb dead)
#define OUTB_OFF  2048     // 16x128
#define SC_OFF    8320     // 32 floats
// aliases inside FEAT region for the tail
#define HB_OFF    (FEAT_OFF + 0)     // 16x64
#define SF_OFF    (FEAT_OFF + 1024)  // 16x64
#define XB_OFF    (FEAT_OFF + 2048)  // 16x76
#define H1_OFF    (FEAT_OFF + 3328)  // 16x76
#define H2_OFF    (FEAT_OFF + 4608)  // 16x64

// ---------------------------------------------------------------------------
// f32x2 packed-FMA helpers (sm_100+)
// ---------------------------------------------------------------------------
__device__ __forceinline__ ull pack2(float lo, float hi) {
    ull r; asm("mov.b64 %0, {%1, %2};" : "=l"(r) : "f"(lo), "f"(hi)); return r;
}
__device__ __forceinline__ void unpack2(ull v, float& lo, float& hi) {
    asm("mov.b64 {%0, %1}, %2;" : "=f"(lo), "=f"(hi) : "l"(v));
}
__device__ __forceinline__ void fma2(ull& d, ull a, ull b) {
    asm("fma.rn.f32x2 %0, %1, %2, %0;" : "+l"(d) : "l"(a), "l"(b));
}

// ---------------------------------------------------------------------------
// Pre-transposed / padded weights ([k][o] layout, zero padded)
// ---------------------------------------------------------------------------
__device__ __align__(16) float g_WT_event[352*192];
__device__ __align__(16) float g_WT_gcn1 [176*64];
__device__ __align__(16) float g_WT_gcn2 [ 64*64];
__device__ __align__(16) float g_WT_att1 [128*128];
__device__ __align__(16) float g_WT_att2 [128*128];
__device__ __align__(16) float g_WT_m1   [128*64];
__device__ __align__(16) float g_WT_m2   [ 64*64];

__global__ void prep_kernel(const float* __restrict__ ew,
                            const float* __restrict__ g1,
                            const float* __restrict__ g2,
                            const float* __restrict__ a1,
                            const float* __restrict__ a2,
                            const float* __restrict__ m1,
                            const float* __restrict__ m2)
{
    int t0 = blockIdx.x*blockDim.x + threadIdx.x;
    int stride = gridDim.x*blockDim.x;
    for (int i = t0; i < 352*192; i += stride) {
        int k = i/192, o = i%192;
        g_WT_event[i] = (k < 347 && o < 172) ? ew[o*347 + k] : 0.f;
    }
    for (int i = t0; i < 176*64; i += stride) {
        int k = i/64, o = i%64;
        g_WT_gcn1[i] = (k < 172) ? g1[o*172 + k] : 0.f;
    }
    for (int i = t0; i < 64*64; i += stride) {
        int k = i/64, o = i%64;
        g_WT_gcn2[i] = g2[o*64 + k];
        g_WT_m2[i]   = m2[o*64 + k];
    }
    for (int i = t0; i < 128*128; i += stride) {
        int k = i/128, o = i%128;
        g_WT_att1[i] = a1[o*128 + k];
        g_WT_att2[i] = a2[o*128 + k];
    }
    for (int i = t0; i < 128*64; i += stride) {
        int k = i/64, o = i%64;
        g_WT_m1[i] = m1[o*128 + k];
    }
}

// ---------------------------------------------------------------------------
// GEMM cores. 4 warps (ty = tid>>5), 32 lanes (tx).
// Thread (ty,tx): rows [ty*RT, ty*RT+RT) processed in chunks of RH,
// column pairs {g*64+2*tx, +1} for g<P. A reads are warp-broadcast LDS.128;
// weights are coalesced LDG.64 batched 4 k's up-front.
// NS = weight row stride. K % 4 == 0, RT % RH == 0.
// ---------------------------------------------------------------------------
template<int NS, int K, int RT, int RH, int P, bool RELU, int NREAL>
__device__ __forceinline__ void gemm_direct(
    const float* __restrict__ Wg, const float* __restrict__ bias,
    const float* __restrict__ A, int sa,
    float* __restrict__ C, int sc, int tid)
{
    const int ty = tid >> 5, tx = tid & 31;
    ull acc[RT][P];
#pragma unroll
    for (int i = 0; i < RT; i++)
#pragma unroll
        for (int g = 0; g < P; g++) acc[i][g] = 0ull;

    const float* wq   = Wg + 2*tx;
    const float* arow = A + ty*RT*sa;

#pragma unroll 1
    for (int k4 = 0; k4 < K; k4 += 4) {
        ull w[4][P];
#pragma unroll
        for (int kk = 0; kk < 4; kk++)
#pragma unroll
            for (int g = 0; g < P; g++)
                w[kk][g] = __ldg(reinterpret_cast<const ull*>(wq + (k4+kk)*NS + g*64));
#pragma unroll
        for (int r0 = 0; r0 < RT; r0 += RH) {
            float4 av[RH];
#pragma unroll
            for (int i = 0; i < RH; i++)
                av[i] = *reinterpret_cast<const float4*>(arow + (r0+i)*sa + k4);
#pragma unroll
            for (int kk = 0; kk < 4; kk++) {
#pragma unroll
                for (int i = 0; i < RH; i++) {
                    float a = (kk==0)?av[i].x:(kk==1)?av[i].y:(kk==2)?av[i].z:av[i].w;
                    ull ad = pack2(a, a);
#pragma unroll
                    for (int g = 0; g < P; g++) fma2(acc[r0+i][g], ad, w[kk][g]);
                }
            }
        }
    }
#pragma unroll
    for (int i = 0; i < RT; i++)
#pragma unroll
        for (int g = 0; g < P; g++) {
            int col = g*64 + 2*tx;
            float x, y; unpack2(acc[i][g], x, y);
            int row = ty*RT + i;
            if (col < NREAL) {
                float v = x + __ldg(&bias[col]);
                if (RELU) v = fmaxf(v, 0.f);
                C[row*sc + col] = v;
            }
            if (col + 1 < NREAL) {
                float v = y + __ldg(&bias[col+1]);
                if (RELU) v = fmaxf(v, 0.f);
                C[row*sc + col + 1] = v;
            }
        }
    __syncthreads();
}

// Chunked variant: A chunk [M][KC] generated into Abuf by functor per chunk.
template<int NS, int K, int KC, int RT, int RH, int P, bool RELU, int NREAL, typename Gen>
__device__ __forceinline__ void gemm_gen(
    const float* __restrict__ Wg, const float* __restrict__ bias,
    float* __restrict__ Abuf, const Gen& gen,
    float* __restrict__ C, int sc, int tid)
{
    const int ty = tid >> 5, tx = tid & 31;
    ull acc[RT][P];
#pragma unroll
    for (int i = 0; i < RT; i++)
#pragma unroll
        for (int g = 0; g < P; g++) acc[i][g] = 0ull;

#pragma unroll 1
    for (int kc = 0; kc < K; kc += KC) {
        __syncthreads();                 // prior chunk's Abuf reads done
        gen(Abuf, kc, tid);
        __syncthreads();
        const float* wq   = Wg + kc*NS + 2*tx;
        const float* arow = Abuf + ty*RT*KC;
#pragma unroll 1
        for (int k4 = 0; k4 < KC; k4 += 4) {
            ull w[4][P];
#pragma unroll
            for (int kk = 0; kk < 4; kk++)
#pragma unroll
                for (int g = 0; g < P; g++)
                    w[kk][g] = __ldg(reinterpret_cast<const ull*>(wq + (k4+kk)*NS + g*64));
#pragma unroll
            for (int r0 = 0; r0 < RT; r0 += RH) {
                float4 av[RH];
#pragma unroll
                for (int i = 0; i < RH; i++)
                    av[i] = *reinterpret_cast<const float4*>(arow + (r0+i)*KC + k4);
#pragma unroll
                for (int kk = 0; kk < 4; kk++) {
#pragma unroll
                    for (int i = 0; i < RH; i++) {
                        float a = (kk==0)?av[i].x:(kk==1)?av[i].y:(kk==2)?av[i].z:av[i].w;
                        ull ad = pack2(a, a);
#pragma unroll
                        for (int g = 0; g < P; g++) fma2(acc[r0+i][g], ad, w[kk][g]);
                    }
                }
            }
        }
    }
#pragma unroll
    for (int i = 0; i < RT; i++)
#pragma unroll
        for (int g = 0; g < P; g++) {
            int col = g*64 + 2*tx;
            float x, y; unpack2(acc[i][g], x, y);
            int row = ty*RT + i;
            if (col < NREAL) {
                float v = x + __ldg(&bias[col]);
                if (RELU) v = fmaxf(v, 0.f);
                C[row*sc + col] = v;
            }
            if (col + 1 < NREAL) {
                float v = y + __ldg(&bias[col+1]);
                if (RELU) v = fmaxf(v, 0.f);
                C[row*sc + col + 1] = v;
            }
        }
    __syncthreads();
}

// ---------------------------------------------------------------------------
// A-chunk generators
// ---------------------------------------------------------------------------
struct EventGen {
    const int*   edge_idx;
    const float* edge_embed;
    const float* edge_identify;
    const float* t_records;
    const float* basis_freq;
    const float* phase;
    int g0;
    __device__ __forceinline__ void operator()(float* Abuf, int kc, int tid) const {
        for (int idx = tid; idx < ROWS*44; idx += NTHREADS) {
            int r = idx / 44, cc = idx - r*44;
            int c = kc + cc;
            int p = r / 3, l = r - p*3;
            int g = g0 + p;
            float v = 0.f;
            if (c < 172) {
                int e = __ldg(&edge_idx[g*3 + l]);
                v = __ldg(&edge_embed[(long)e*172 + c]);
            } else if (c < 175) {
                v = __ldg(&edge_identify[(g*3 + l)*3 + (c - 172)]);
            } else if (c < 347) {
                int d = c - 175;
                float dt = __ldg(&t_records[g*3 + 2]) - __ldg(&t_records[g*3 + l]);
                v = __cosf(dt * __ldg(&basis_freq[d]) + __ldg(&phase[d]));
            }
            Abuf[idx] = v;
        }
    }
};

struct GineGen {
    const int*   node_idx;
    const float* node_embed;
    const float* evt;   // smem, pitch 176
    int g0;
    int swap;
    __device__ __forceinline__ void operator()(float* Abuf, int kc, int tid) const {
        for (int idx = tid; idx < ROWS*44; idx += NTHREADS) {
            int r = idx / 44, cc = idx - r*44;
            int c = kc + cc;
            int p = r / 3, l = r - p*3;
            int g = g0 + p;
            float v = 0.f;
            if (c < 172) {
                int ns = __ldg(&node_idx[g*6 + 2*l]);
                int nt = __ldg(&node_idx[g*6 + 2*l + 1]);
                float s = __ldg(&node_embed[(long)ns*172 + c]);
                float t = __ldg(&node_embed[(long)nt*172 + c]);
                float e = evt[r*176 + c];
                v = swap ? (t + fmaxf(s + e, 0.f)) : (s + fmaxf(t + e, 0.f));
            }
            Abuf[idx] = v;
        }
    }
};

// ---------------------------------------------------------------------------
// Fused main kernel: one block (4 warps) handles 16 (b,w) pairs end-to-end.
// ---------------------------------------------------------------------------
__global__ void __launch_bounds__(NTHREADS, 3)
fused_kernel(const int*   __restrict__ node_idx,
             const int*   __restrict__ edge_idx,
             const int*   __restrict__ cat_feat,
             const float* __restrict__ t_records,
             const float* __restrict__ edge_identify,
             const float* __restrict__ node_embed,
             const float* __restrict__ edge_embed,
             const float* __restrict__ basis_freq,
             const float* __restrict__ phase,
             const float* __restrict__ lin_event_b,
             const float* __restrict__ gcn_b1,
             const float* __restrict__ gcn_b2,
             const float* __restrict__ att_w1_b,
             const float* __restrict__ att_w2_b,
             const float* __restrict__ att_m1_b,
             const float* __restrict__ att_m2_b,
             const float* __restrict__ mlp_w1,
             const float* __restrict__ mlp_b1,
             const float* __restrict__ mlp_w2,
             const float* __restrict__ mlp_b2,
             const float* __restrict__ mlp_w3,
             const float* __restrict__ mlp_b3,
             float*       __restrict__ out)
{
    extern __shared__ float sm[];
    const int tid = threadIdx.x;
    const int g0  = blockIdx.x * PAIRS;

    float* evt  = sm + EVT_OFF;
    float* feat = sm + FEAT_OFF;
    float* Abuf = sm + ABUF_OFF;

    // ---- Phase 1: event linear (K padded 352, N stride 192, real 172) ----
    EventGen eg{edge_idx, edge_embed, edge_identify, t_records, basis_freq, phase, g0};
    gemm_gen<192,352,44,12,6,3,false,172>(g_WT_event, lin_event_b, Abuf, eg, evt, 176, tid);

    // ---- Phase 2: gine(src,tgt) -> feat[:,0:64] ----
    GineGen gg1{node_idx, node_embed, evt, g0, 0};
    gemm_gen<64,176,44,12,6,1,true,64>(g_WT_gcn1, gcn_b1, Abuf, gg1, feat + 64, 128, tid);
    gemm_direct<64,64,12,6,1,false,64>(g_WT_gcn2, gcn_b2, feat + 64, 128, feat + 0, 128, tid);

    // ---- Phase 3: gine(tgt,src) -> feat[:,64:128]  (H lives in evt, dead) --
    GineGen gg2{node_idx, node_embed, evt, g0, 1};
    gemm_gen<64,176,44,12,6,1,true,64>(g_WT_gcn1, gcn_b1, Abuf, gg2, evt, 64, tid);
    gemm_direct<64,64,12,6,1,false,64>(g_WT_gcn2, gcn_b2, evt, 64, feat + 64, 128, tid);

    // ---- Phase 4: attention ----
    float* tgtb = sm + TGTB_OFF;
    for (int idx = tid; idx < 32*128; idx += NTHREADS) {
        int r = idx >> 7, c = idx & 127;
        tgtb[idx] = feat[((r >> 1)*3 + (r & 1))*128 + c];
    }
    __syncthreads();
    float* Wq = sm + WQ_OFF;
    gemm_direct<128,128,8,8,2,false,128>(g_WT_att2, att_w2_b, tgtb, 128, Wq, 128, tid);
    float* Wp = sm + WP_OFF;   // overwrites tgtb (dead)
    gemm_direct<128,128,4,4,2,false,128>(g_WT_att1, att_w1_b, feat + 256, 384, Wp, 128, tid);

    float* scb = sm + SC_OFF;
    {
        int pk = tid >> 2, sub = tid & 3;   // pk 0..31, 4 lanes per score
        int p = pk >> 1, k = pk & 1;
        float s = 0.f;
        for (int j = sub; j < 128; j += 4)
            s += Wp[p*128 + j] * Wq[(2*p + k)*128 + j];
        s += __shfl_down_sync(0xffffffffu, s, 2, 4);
        s += __shfl_down_sync(0xffffffffu, s, 1, 4);
        if (sub == 0) scb[pk] = s;
    }
    __syncthreads();
    if (tid < PAIRS) {
        float s0 = scb[2*tid], s1 = scb[2*tid + 1];
        float m = fmaxf(s0, s1);
        float e0 = __expf(s0 - m), e1 = __expf(s1 - m);
        float inv = 1.f / (e0 + e1);
        scb[2*tid]     = e0 * inv;
        scb[2*tid + 1] = e1 * inv;
    }
    __syncthreads();
    float* outb = sm + OUTB_OFF;
    for (int idx = tid; idx < PAIRS*128; idx += NTHREADS) {
        int p = idx >> 7, c = idx & 127;
        outb[idx] = feat[(p*3 + 2)*128 + c]
                  + scb[2*p]     * Wq[(2*p)*128 + c]
                  + scb[2*p + 1] * Wq[(2*p + 1)*128 + c];
    }
    __syncthreads();

    float* hb = sm + HB_OFF;
    float* sf = sm + SF_OFF;
    gemm_direct<64,128,4,4,1,true,64>(g_WT_m1, att_m1_b, outb, 128, hb, 64, tid);
    gemm_direct<64,64,4,4,1,false,64>(g_WT_m2, att_m2_b, hb, 64, sf, 64, tid);

    // ---- Phase 5: MLP tail ----
    float* xb  = sm + XB_OFF;
    float* h1b = sm + H1_OFF;
    float* h2b = sm + H2_OFF;
    for (int idx = tid; idx < PAIRS*76; idx += NTHREADS) {
        int p = idx / 76, c = idx - p*76;
        float v;
        if (c < 64) v = sf[p*64 + c];
        else        v = (__ldg(&cat_feat[g0 + p]) == (c - 64)) ? 1.f : 0.f;
        xb[idx] = v;
    }
    __syncthreads();
    for (int idx = tid; idx < PAIRS*76; idx += NTHREADS) {
        int p = idx / 76, c = idx - p*76;
        const float* w = mlp_w1 + c*76;
        const float* x = xb + p*76;
        float s = __ldg(&mlp_b1[c]);
#pragma unroll 4
        for (int k = 0; k < 76; k++) s += x[k] * __ldg(&w[k]);
        h1b[idx] = fmaxf(s, 0.f);
    }
    __syncthreads();
    for (int idx = tid; idx < PAIRS*64; idx += NTHREADS) {
        int p = idx >> 6, c = idx & 63;
        const float* w = mlp_w2 + c*76;
        const float* x = h1b + p*76;
        float s = __ldg(&mlp_b2[c]);
#pragma unroll 4
        for (int k = 0; k < 76; k++) s += x[k] * __ldg(&w[k]);
        h2b[idx] = fmaxf(s, 0.f);
    }
    __syncthreads();
    if (tid < PAIRS) {
        float z = __ldg(&mlp_b3[0]);
        const float* x = h2b + tid*64;
#pragma unroll 4
        for (int k = 0; k < 64; k++) z += x[k] * __ldg(&mlp_w3[k]);
        out[g0 + tid] = 1.f / (1.f + __expf(-z));
    }
}

// ---------------------------------------------------------------------------
// Launch
// ---------------------------------------------------------------------------
extern "C" void kernel_launch(void* const* d_in, const int* in_sizes, int n_in,
                              void* d_out, int out_size)
{
    const int*   node_idx      = (const int*)  d_in[0];
    const int*   edge_idx      = (const int*)  d_in[1];
    const int*   cat_feat      = (const int*)  d_in[2];
    const float* t_records     = (const float*)d_in[3];
    const float* edge_identify = (const float*)d_in[4];
    // d_in[5] = cut_time_l (unused by reference)
    const float* node_embed    = (const float*)d_in[6];
    const float* edge_embed    = (const float*)d_in[7];
    const float* basis_freq    = (const float*)d_in[8];
    const float* phase         = (const float*)d_in[9];
    const float* lin_event_w   = (const float*)d_in[10];
    const float* lin_event_b   = (const float*)d_in[11];
    const float* gcn_w1        = (const float*)d_in[12];
    const float* gcn_b1        = (const float*)d_in[13];
    const float* gcn_w2        = (const float*)d_in[14];
    const float* gcn_b2        = (const float*)d_in[15];
    const float* att_w1_w      = (const float*)d_in[16];
    const float* att_w1_b      = (const float*)d_in[17];
    const float* att_w2_w      = (const float*)d_in[18];
    const float* att_w2_b      = (const float*)d_in[19];
    const float* att_m1_w      = (const float*)d_in[20];
    const float* att_m1_b      = (const float*)d_in[21];
    const float* att_m2_w      = (const float*)d_in[22];
    const float* att_m2_b      = (const float*)d_in[23];
    const float* mlp_w1        = (const float*)d_in[24];
    const float* mlp_b1        = (const float*)d_in[25];
    const float* mlp_w2        = (const float*)d_in[26];
    const float* mlp_b2        = (const float*)d_in[27];
    const float* mlp_w3        = (const float*)d_in[28];
    const float* mlp_b3        = (const float*)d_in[29];
    float* outp = (float*)d_out;

    cudaFuncSetAttribute(fused_kernel,
                         cudaFuncAttributeMaxDynamicSharedMemorySize, SMEM_BYTES);

    prep_kernel<<<128, 256>>>(lin_event_w, gcn_w1, gcn_w2,
                              att_w1_w, att_w2_w, att_m1_w, att_m2_w);

    fused_kernel<<<NBLK, NTHREADS, SMEM_BYTES>>>(
        node_idx, edge_idx, cat_feat, t_records, edge_identify,
        node_embed, edge_embed, basis_freq, phase,
        lin_event_b, gcn_b1, gcn_b2,
        att_w1_b, att_w2_b, att_m1_b, att_m2_b,
        mlp_w1, mlp_b1, mlp_w2, mlp_b2, mlp_w3, mlp_b3,
        outp);
}

// round 6
// speedup vs baseline: 1.2165x; 1.2165x over previous
#include <cuda_runtime.h>
#include <math.h>

#define NTHREADS 256
#define PAIRS    16
#define ROWS     48        // PAIRS*3
#define NBLK     2048      // 32768/PAIRS

typedef unsigned long long ull;

// ---------------------------------------------------------------------------
// smem layout (floats): 18816 floats = 75264 B -> 3 blocks/SM (~226KB)
// ---------------------------------------------------------------------------
#define EVT_OFF   0        // 48*176 = 8448
#define FEAT_OFF  8448     // 48*128 = 6144
#define ABUF_OFF  14592    // 2*48*44 = 4224 (event double buffer / gine dual)
#define SMEM_FLOATS 18816
#define SMEM_BYTES (SMEM_FLOATS*4)
// aliases inside EVT region
#define GH1_OFF   (EVT_OFF + 0)      // gine hidden 1: 48x64 (pitch 64)
#define GH2_OFF   (EVT_OFF + 3072)   // gine hidden 2: 48x64
#define TGTB_OFF  (EVT_OFF + 0)      // 32x128
#define WQ_OFF    (EVT_OFF + 4096)   // 32x128
#define WP_OFF    (EVT_OFF + 0)      // 16x128 (tgtb dead)
// aliases inside ABUF region
#define OUTB_OFF  (ABUF_OFF + 0)     // 16x128 = 2048
#define SC_OFF    (ABUF_OFF + 2048)  // 32 floats
// aliases inside FEAT region for the tail (feat dead after outb built)
#define HB_OFF    (FEAT_OFF + 0)     // 16x64
#define SF_OFF    (FEAT_OFF + 1024)  // 16x64
#define XB_OFF    (FEAT_OFF + 2048)  // 16x76
#define H1_OFF    (FEAT_OFF + 3264)  // 16x76
#define H2_OFF    (FEAT_OFF + 4480)  // 16x64

// ---------------------------------------------------------------------------
// f32x2 packed-FMA helpers (sm_100+)
// ---------------------------------------------------------------------------
__device__ __forceinline__ ull pack2(float lo, float hi) {
    ull r; asm("mov.b64 %0, {%1, %2};" : "=l"(r) : "f"(lo), "f"(hi)); return r;
}
__device__ __forceinline__ void unpack2(ull v, float& lo, float& hi) {
    asm("mov.b64 {%0, %1}, %2;" : "=f"(lo), "=f"(hi) : "l"(v));
}
__device__ __forceinline__ void fma2(ull& d, ull a, ull b) {
    asm("fma.rn.f32x2 %0, %1, %2, %0;" : "+l"(d) : "l"(a), "l"(b));
}
__device__ __forceinline__ float fsel4(float4 v, int kk) {
    return (kk==0)?v.x:(kk==1)?v.y:(kk==2)?v.z:v.w;
}

// ---------------------------------------------------------------------------
// Pre-transposed / padded weights ([k][o] layout, zero padded)
// ---------------------------------------------------------------------------
__device__ __align__(16) float g_WT_event[352*192];
__device__ __align__(16) float g_WT_gcn1 [176*64];
__device__ __align__(16) float g_WT_gcn2 [ 64*64];
__device__ __align__(16) float g_WT_att1 [128*128];
__device__ __align__(16) float g_WT_att2 [128*128];
__device__ __align__(16) float g_WT_m1   [128*64];
__device__ __align__(16) float g_WT_m2   [ 64*64];

__global__ void prep_kernel(const float* __restrict__ ew,
                            const float* __restrict__ g1,
                            const float* __restrict__ g2,
                            const float* __restrict__ a1,
                            const float* __restrict__ a2,
                            const float* __restrict__ m1,
                            const float* __restrict__ m2)
{
    int t0 = blockIdx.x*blockDim.x + threadIdx.x;
    int stride = gridDim.x*blockDim.x;
    for (int i = t0; i < 352*192; i += stride) {
        int k = i/192, o = i%192;
        g_WT_event[i] = (k < 347 && o < 172) ? ew[o*347 + k] : 0.f;
    }
    for (int i = t0; i < 176*64; i += stride) {
        int k = i/64, o = i%64;
        g_WT_gcn1[i] = (k < 172) ? g1[o*172 + k] : 0.f;
    }
    for (int i = t0; i < 64*64; i += stride) {
        int k = i/64, o = i%64;
        g_WT_gcn2[i] = g2[o*64 + k];
        g_WT_m2[i]   = m2[o*64 + k];
    }
    for (int i = t0; i < 128*128; i += stride) {
        int k = i/128, o = i%128;
        g_WT_att1[i] = a1[o*128 + k];
        g_WT_att2[i] = a2[o*128 + k];
    }
    for (int i = t0; i < 128*64; i += stride) {
        int k = i/64, o = i%64;
        g_WT_m1[i] = m1[o*128 + k];
    }
}

// ---------------------------------------------------------------------------
// Direct GEMM: 8 warps, thread (ty,tx) computes rows [ty*RT,..+RT),
// cols {g*64+2tx,+1}, weights from global, batched 4 k's up-front.
// ---------------------------------------------------------------------------
template<int NS, int K, int RT, int P, bool RELU, int NREAL>
__device__ __forceinline__ void gemm_direct(
    const float* __restrict__ Wg, const float* __restrict__ bias,
    const float* __restrict__ A, int sa,
    float* __restrict__ C, int sc, int tid)
{
    const int ty = tid >> 5, tx = tid & 31;
    ull acc[RT][P];
#pragma unroll
    for (int i = 0; i < RT; i++)
#pragma unroll
        for (int g = 0; g < P; g++) acc[i][g] = 0ull;

    const float* wq   = Wg + 2*tx;
    const float* arow = A + ty*RT*sa;

#pragma unroll 1
    for (int k4 = 0; k4 < K; k4 += 4) {
        ull w[4][P];
#pragma unroll
        for (int kk = 0; kk < 4; kk++)
#pragma unroll
            for (int g = 0; g < P; g++)
                w[kk][g] = __ldg(reinterpret_cast<const ull*>(wq + (k4+kk)*NS + g*64));
        float4 av[RT];
#pragma unroll
        for (int i = 0; i < RT; i++)
            av[i] = *reinterpret_cast<const float4*>(arow + i*sa + k4);
#pragma unroll
        for (int kk = 0; kk < 4; kk++)
#pragma unroll
            for (int i = 0; i < RT; i++) {
                ull ad = pack2(fsel4(av[i],kk), fsel4(av[i],kk));
#pragma unroll
                for (int g = 0; g < P; g++) fma2(acc[i][g], ad, w[kk][g]);
            }
    }
#pragma unroll
    for (int i = 0; i < RT; i++)
#pragma unroll
        for (int g = 0; g < P; g++) {
            int col = g*64 + 2*tx;
            float x, y; unpack2(acc[i][g], x, y);
            int row = ty*RT + i;
            if (col < NREAL) {
                float v = x + __ldg(&bias[col]);
                if (RELU) v = fmaxf(v, 0.f);
                C[row*sc + col] = v;
            }
            if (col + 1 < NREAL) {
                float v = y + __ldg(&bias[col+1]);
                if (RELU) v = fmaxf(v, 0.f);
                C[row*sc + col + 1] = v;
            }
        }
    __syncthreads();
}

// ---------------------------------------------------------------------------
// Event generator (one 48x44 chunk of event_f)
// ---------------------------------------------------------------------------
struct EventGen {
    const int*   edge_idx;
    const float* edge_embed;
    const float* edge_identify;
    const float* t_records;
    const float* basis_freq;
    const float* phase;
    int g0;
    __device__ __forceinline__ void operator()(float* Abuf, int kc, int tid) const {
        for (int idx = tid; idx < ROWS*44; idx += NTHREADS) {
            int r = idx / 44, cc = idx - r*44;
            int c = kc + cc;
            int p = r / 3, l = r - p*3;
            int g = g0 + p;
            float v = 0.f;
            if (c < 172) {
                int e = __ldg(&edge_idx[g*3 + l]);
                v = __ldg(&edge_embed[(long)e*172 + c]);
            } else if (c < 175) {
                v = __ldg(&edge_identify[(g*3 + l)*3 + (c - 172)]);
            } else if (c < 347) {
                int d = c - 175;
                float dt = __ldg(&t_records[g*3 + 2]) - __ldg(&t_records[g*3 + l]);
                v = __cosf(dt * __ldg(&basis_freq[d]) + __ldg(&phase[d]));
            }
            Abuf[idx] = v;
        }
    }
};

// ---------------------------------------------------------------------------
// Event GEMM with double-buffered generation.
// K=352 (8 chunks of 44), N stride 192, real 172, RT=6, P=3.
// ---------------------------------------------------------------------------
__device__ __forceinline__ void gemm_event(
    const float* __restrict__ bias,
    float* __restrict__ Abuf, const EventGen& gen,
    float* __restrict__ C, int tid)
{
    const int ty = tid >> 5, tx = tid & 31;
    ull acc[6][3];
#pragma unroll
    for (int i = 0; i < 6; i++)
#pragma unroll
        for (int g = 0; g < 3; g++) acc[i][g] = 0ull;

    gen(Abuf, 0, tid);
    __syncthreads();
#pragma unroll 1
    for (int kc = 0; kc < 352; kc += 44) {
        int buf = (kc / 44) & 1;
        const float* cur = Abuf + buf*2112;
        if (kc + 44 < 352) gen(Abuf + (buf^1)*2112, kc + 44, tid);
        const float* wq   = g_WT_event + kc*192 + 2*tx;
        const float* arow = cur + ty*6*44;
#pragma unroll 1
        for (int k4 = 0; k4 < 44; k4 += 4) {
            float4 av[6];
#pragma unroll
            for (int i = 0; i < 6; i++)
                av[i] = *reinterpret_cast<const float4*>(arow + i*44 + k4);
#pragma unroll
            for (int kk = 0; kk < 4; kk++) {
                ull w[3];
#pragma unroll
                for (int g = 0; g < 3; g++)
                    w[g] = __ldg(reinterpret_cast<const ull*>(wq + (k4+kk)*192 + g*64));
#pragma unroll
                for (int i = 0; i < 6; i++) {
                    ull ad = pack2(fsel4(av[i],kk), fsel4(av[i],kk));
#pragma unroll
                    for (int g = 0; g < 3; g++) fma2(acc[i][g], ad, w[g]);
                }
            }
        }
        __syncthreads();
    }
#pragma unroll
    for (int i = 0; i < 6; i++)
#pragma unroll
        for (int g = 0; g < 3; g++) {
            int col = g*64 + 2*tx;
            float x, y; unpack2(acc[i][g], x, y);
            int row = ty*6 + i;
            if (col < 172)     C[row*176 + col]     = x + __ldg(&bias[col]);
            if (col + 1 < 172) C[row*176 + col + 1] = y + __ldg(&bias[col+1]);
        }
    __syncthreads();
}

// ---------------------------------------------------------------------------
// Dual gine: one gen produces in1 = s+relu(t+e) and in2 = t+relu(s+e);
// one GEMM loop accumulates both against shared gcn1 weight loads.
// Outputs H1 -> C1, H2 -> C2 (pitch 64), relu applied.
// ---------------------------------------------------------------------------
struct GineDualGen {
    const int*   node_idx;
    const float* node_embed;
    const float* evt;   // smem, pitch 176
    int g0;
    __device__ __forceinline__ void operator()(float* Abuf, int kc, int tid) const {
        for (int idx = tid; idx < ROWS*44; idx += NTHREADS) {
            int r = idx / 44, cc = idx - r*44;
            int c = kc + cc;
            int p = r / 3, l = r - p*3;
            int g = g0 + p;
            float v1 = 0.f, v2 = 0.f;
            if (c < 172) {
                int ns = __ldg(&node_idx[g*6 + 2*l]);
                int nt = __ldg(&node_idx[g*6 + 2*l + 1]);
                float s = __ldg(&node_embed[(long)ns*172 + c]);
                float t = __ldg(&node_embed[(long)nt*172 + c]);
                float e = evt[r*176 + c];
                v1 = s + fmaxf(t + e, 0.f);
                v2 = t + fmaxf(s + e, 0.f);
            }
            Abuf[idx]        = v1;
            Abuf[2112 + idx] = v2;
        }
    }
};

__device__ __forceinline__ void gemm_gine_dual(
    const float* __restrict__ bias,
    float* __restrict__ Abuf, const GineDualGen& gen,
    float* __restrict__ C1, float* __restrict__ C2, int tid)
{
    const int ty = tid >> 5, tx = tid & 31;
    ull acc1[6], acc2[6];
#pragma unroll
    for (int i = 0; i < 6; i++) { acc1[i] = 0ull; acc2[i] = 0ull; }

#pragma unroll 1
    for (int kc = 0; kc < 176; kc += 44) {
        __syncthreads();            // prior chunk's Abuf reads done
        gen(Abuf, kc, tid);
        __syncthreads();
        const float* wq = g_WT_gcn1 + kc*64 + 2*tx;
        const float* a1row = Abuf + ty*6*44;
        const float* a2row = Abuf + 2112 + ty*6*44;
#pragma unroll 1
        for (int k4 = 0; k4 < 44; k4 += 4) {
            ull w[4];
#pragma unroll
            for (int kk = 0; kk < 4; kk++)
                w[kk] = __ldg(reinterpret_cast<const ull*>(wq + (k4+kk)*64));
#pragma unroll
            for (int i = 0; i < 6; i++) {
                float4 a1 = *reinterpret_cast<const float4*>(a1row + i*44 + k4);
                float4 a2 = *reinterpret_cast<const float4*>(a2row + i*44 + k4);
#pragma unroll
                for (int kk = 0; kk < 4; kk++) {
                    fma2(acc1[i], pack2(fsel4(a1,kk), fsel4(a1,kk)), w[kk]);
                    fma2(acc2[i], pack2(fsel4(a2,kk), fsel4(a2,kk)), w[kk]);
                }
            }
        }
    }
    int col = 2*tx;
    float b0 = __ldg(&bias[col]), b1 = __ldg(&bias[col+1]);
#pragma unroll
    for (int i = 0; i < 6; i++) {
        int row = ty*6 + i;
        float x, y;
        unpack2(acc1[i], x, y);
        C1[row*64 + col]     = fmaxf(x + b0, 0.f);
        C1[row*64 + col + 1] = fmaxf(y + b1, 0.f);
        unpack2(acc2[i], x, y);
        C2[row*64 + col]     = fmaxf(x + b0, 0.f);
        C2[row*64 + col + 1] = fmaxf(y + b1, 0.f);
    }
    __syncthreads();
}

// Dual gcn2: H1,H2 (pitch 64) -> feat[:,0:64] and feat[:,64:128], shared weights.
__device__ __forceinline__ void gemm_gcn2_dual(
    const float* __restrict__ bias,
    const float* __restrict__ H1, const float* __restrict__ H2,
    float* __restrict__ feat, int tid)
{
    const int ty = tid >> 5, tx = tid & 31;
    ull acc1[6], acc2[6];
#pragma unroll
    for (int i = 0; i < 6; i++) { acc1[i] = 0ull; acc2[i] = 0ull; }
    const float* wq = g_WT_gcn2 + 2*tx;
#pragma unroll 1
    for (int k4 = 0; k4 < 64; k4 += 4) {
        ull w[4];
#pragma unroll
        for (int kk = 0; kk < 4; kk++)
            w[kk] = __ldg(reinterpret_cast<const ull*>(wq + (k4+kk)*64));
#pragma unroll
        for (int i = 0; i < 6; i++) {
            float4 a1 = *reinterpret_cast<const float4*>(H1 + (ty*6+i)*64 + k4);
            float4 a2 = *reinterpret_cast<const float4*>(H2 + (ty*6+i)*64 + k4);
#pragma unroll
            for (int kk = 0; kk < 4; kk++) {
                fma2(acc1[i], pack2(fsel4(a1,kk), fsel4(a1,kk)), w[kk]);
                fma2(acc2[i], pack2(fsel4(a2,kk), fsel4(a2,kk)), w[kk]);
            }
        }
    }
    __syncthreads();   // H1/H2 live in evt; ensure reads done before feat writes? (disjoint) — keep for Abuf reuse safety
    int col = 2*tx;
    float b0 = __ldg(&bias[col]), b1 = __ldg(&bias[col+1]);
#pragma unroll
    for (int i = 0; i < 6; i++) {
        int row = ty*6 + i;
        float x, y;
        unpack2(acc1[i], x, y);
        feat[row*128 + col]      = x + b0;
        feat[row*128 + col + 1]  = y + b1;
        unpack2(acc2[i], x, y);
        feat[row*128 + 64 + col]     = x + b0;
        feat[row*128 + 64 + col + 1] = y + b1;
    }
    __syncthreads();
}

// ---------------------------------------------------------------------------
// Fused main kernel: one block (8 warps) handles 16 (b,w) pairs end-to-end.
// ---------------------------------------------------------------------------
__global__ void __launch_bounds__(NTHREADS, 3)
fused_kernel(const int*   __restrict__ node_idx,
             const int*   __restrict__ edge_idx,
             const int*   __restrict__ cat_feat,
             const float* __restrict__ t_records,
             const float* __restrict__ edge_identify,
             const float* __restrict__ node_embed,
             const float* __restrict__ edge_embed,
             const float* __restrict__ basis_freq,
             const float* __restrict__ phase,
             const float* __restrict__ lin_event_b,
             const float* __restrict__ gcn_b1,
             const float* __restrict__ gcn_b2,
             const float* __restrict__ att_w1_b,
             const float* __restrict__ att_w2_b,
             const float* __restrict__ att_m1_b,
             const float* __restrict__ att_m2_b,
             const float* __restrict__ mlp_w1,
             const float* __restrict__ mlp_b1,
             const float* __restrict__ mlp_w2,
             const float* __restrict__ mlp_b2,
             const float* __restrict__ mlp_w3,
             const float* __restrict__ mlp_b3,
             float*       __restrict__ out)
{
    extern __shared__ float sm[];
    const int tid = threadIdx.x;
    const int g0  = blockIdx.x * PAIRS;

    float* evt  = sm + EVT_OFF;
    float* feat = sm + FEAT_OFF;
    float* Abuf = sm + ABUF_OFF;

    // ---- Phase 1: event linear (double-buffered gen) ----
    EventGen eg{edge_idx, edge_embed, edge_identify, t_records, basis_freq, phase, g0};
    gemm_event(lin_event_b, Abuf, eg, evt, tid);

    // ---- Phase 2: dual gine -> GH1/GH2 (in evt region, evt consumed by gen) ----
    GineDualGen gg{node_idx, node_embed, evt, g0};
    gemm_gine_dual(gcn_b1, Abuf, gg, sm + GH1_OFF, sm + GH2_OFF, tid);

    // ---- Phase 3: dual gcn2 -> feat[:,0:64] & feat[:,64:128] ----
    gemm_gcn2_dual(gcn_b2, sm + GH1_OFF, sm + GH2_OFF, feat, tid);

    // ---- Phase 4: attention ----
    float* tgtb = sm + TGTB_OFF;
    for (int idx = tid; idx < 32*128; idx += NTHREADS) {
        int r = idx >> 7, c = idx & 127;
        tgtb[idx] = feat[((r >> 1)*3 + (r & 1))*128 + c];
    }
    __syncthreads();
    float* Wq = sm + WQ_OFF;
    gemm_direct<128,128,4,2,false,128>(g_WT_att2, att_w2_b, tgtb, 128, Wq, 128, tid);
    float* Wp = sm + WP_OFF;   // overwrites tgtb (dead)
    gemm_direct<128,128,2,2,false,128>(g_WT_att1, att_w1_b, feat + 256, 384, Wp, 128, tid);

    float* scb = sm + SC_OFF;
    {
        int pk = tid >> 3, sub = tid & 7;   // pk 0..31
        int p = pk >> 1, k = pk & 1;
        float s = 0.f;
        for (int j = sub; j < 128; j += 8)
            s += Wp[p*128 + j] * Wq[(2*p + k)*128 + j];
        s += __shfl_down_sync(0xffffffffu, s, 4, 8);
        s += __shfl_down_sync(0xffffffffu, s, 2, 8);
        s += __shfl_down_sync(0xffffffffu, s, 1, 8);
        if (sub == 0) scb[pk] = s;
    }
    __syncthreads();
    if (tid < PAIRS) {
        float s0 = scb[2*tid], s1 = scb[2*tid + 1];
        float m = fmaxf(s0, s1);
        float e0 = __expf(s0 - m), e1 = __expf(s1 - m);
        float inv = 1.f / (e0 + e1);
        scb[2*tid]     = e0 * inv;
        scb[2*tid + 1] = e1 * inv;
    }
    __syncthreads();
    float* outb = sm + OUTB_OFF;
    for (int idx = tid; idx < PAIRS*128; idx += NTHREADS) {
        int p = idx >> 7, c = idx & 127;
        outb[idx] = feat[(p*3 + 2)*128 + c]
                  + scb[2*p]     * Wq[(2*p)*128 + c]
                  + scb[2*p + 1] * Wq[(2*p + 1)*128 + c];
    }
    __syncthreads();

    float* hb = sm + HB_OFF;
    float* sf = sm + SF_OFF;
    gemm_direct<64,128,2,1,true,64>(g_WT_m1, att_m1_b, outb, 128, hb, 64, tid);
    gemm_direct<64,64,2,1,false,64>(g_WT_m2, att_m2_b, hb, 64, sf, 64, tid);

    // ---- Phase 5: MLP tail ----
    float* xb  = sm + XB_OFF;
    float* h1b = sm + H1_OFF;
    float* h2b = sm + H2_OFF;
    for (int idx = tid; idx < PAIRS*76; idx += NTHREADS) {
        int p = idx / 76, c = idx - p*76;
        float v;
        if (c < 64) v = sf[p*64 + c];
        else        v = (__ldg(&cat_feat[g0 + p]) == (c - 64)) ? 1.f : 0.f;
        xb[idx] = v;
    }
    __syncthreads();
    for (int idx = tid; idx < PAIRS*76; idx += NTHREADS) {
        int p = idx / 76, c = idx - p*76;
        const float* w = mlp_w1 + c*76;
        const float* x = xb + p*76;
        float s = __ldg(&mlp_b1[c]);
#pragma unroll 4
        for (int k = 0; k < 76; k++) s += x[k] * __ldg(&w[k]);
        h1b[idx] = fmaxf(s, 0.f);
    }
    __syncthreads();
    for (int idx = tid; idx < PAIRS*64; idx += NTHREADS) {
        int p = idx >> 6, c = idx & 63;
        const float* w = mlp_w2 + c*76;
        const float* x = h1b + p*76;
        float s = __ldg(&mlp_b2[c]);
#pragma unroll 4
        for (int k = 0; k < 76; k++) s += x[k] * __ldg(&w[k]);
        h2b[idx] = fmaxf(s, 0.f);
    }
    __syncthreads();
    if (tid < PAIRS) {
        float z = __ldg(&mlp_b3[0]);
        const float* x = h2b + tid*64;
#pragma unroll 4
        for (int k = 0; k < 64; k++) z += x[k] * __ldg(&mlp_w3[k]);
        out[g0 + tid] = 1.f / (1.f + __expf(-z));
    }
}

// ---------------------------------------------------------------------------
// Launch
// ---------------------------------------------------------------------------
extern "C" void kernel_launch(void* const* d_in, const int* in_sizes, int n_in,
                              void* d_out, int out_size)
{
    const int*   node_idx      = (const int*)  d_in[0];
    const int*   edge_idx      = (const int*)  d_in[1];
    const int*   cat_feat      = (const int*)  d_in[2];
    const float* t_records     = (const float*)d_in[3];
    const float* edge_identify = (const float*)d_in[4];
    // d_in[5] = cut_time_l (unused by reference)
    const float* node_embed    = (const float*)d_in[6];
    const float* edge_embed    = (const float*)d_in[7];
    const float* basis_freq    = (const float*)d_in[8];
    const float* phase         = (const float*)d_in[9];
    const float* lin_event_w   = (const float*)d_in[10];
    const float* lin_event_b   = (const float*)d_in[11];
    const float* gcn_w1        = (const float*)d_in[12];
    const float* gcn_b1        = (const float*)d_in[13];
    const float* gcn_w2        = (const float*)d_in[14];
    const float* gcn_b2        = (const float*)d_in[15];
    const float* att_w1_w      = (const float*)d_in[16];
    const float* att_w1_b      = (const float*)d_in[17];
    const float* att_w2_w      = (const float*)d_in[18];
    const float* att_w2_b      = (const float*)d_in[19];
    const float* att_m1_w      = (const float*)d_in[20];
    const float* att_m1_b      = (const float*)d_in[21];
    const float* att_m2_w      = (const float*)d_in[22];
    const float* att_m2_b      = (const float*)d_in[23];
    const float* mlp_w1        = (const float*)d_in[24];
    const float* mlp_b1        = (const float*)d_in[25];
    const float* mlp_w2        = (const float*)d_in[26];
    const float* mlp_b2        = (const float*)d_in[27];
    const float* mlp_w3        = (const float*)d_in[28];
    const float* mlp_b3        = (const float*)d_in[29];
    float* outp = (float*)d_out;

    cudaFuncSetAttribute(fused_kernel,
                         cudaFuncAttributeMaxDynamicSharedMemorySize, SMEM_BYTES);

    prep_kernel<<<128, 256>>>(lin_event_w, gcn_w1, gcn_w2,
                              att_w1_w, att_w2_w, att_m1_w, att_m2_w);

    fused_kernel<<<NBLK, NTHREADS, SMEM_BYTES>>>(
        node_idx, edge_idx, cat_feat, t_records, edge_identify,
        node_embed, edge_embed, basis_freq, phase,
        lin_event_b, gcn_b1, gcn_b2,
        att_w1_b, att_w2_b, att_m1_b, att_m2_b,
        mlp_w1, mlp_b1, mlp_w2, mlp_b2, mlp_w3, mlp_b3,
        outp);
}